// round 1
// baseline (speedup 1.0000x reference)
#include <cuda_runtime.h>

// Problem constants
#define Bc 2
#define Lc 2048
#define Kc 30
#define Hc 128
#define RBFN 16
#define NFN 267   // node features: 15 dir + 12 angle + 240 rbf
#define NFE 121   // edge features: 18 dir + 7 ori + 96 rbf

// Scratch (device globals: allocation-free rule)
__device__ int   g_eidx[Bc*Lc*Kc];
__device__ float g_O[Bc*Lc*9];
__device__ int   g_last[Bc];

struct F3 { float x, y, z; };
__device__ __forceinline__ F3 f3sub(F3 a, F3 b){ return {a.x-b.x, a.y-b.y, a.z-b.z}; }
__device__ __forceinline__ float dot3(F3 a, F3 b){ return a.x*b.x + a.y*b.y + a.z*b.z; }
__device__ __forceinline__ F3 cross3(F3 a, F3 b){
    return { a.y*b.z - a.z*b.y, a.z*b.x - a.x*b.z, a.x*b.y - a.y*b.x };
}
__device__ __forceinline__ F3 norm3v(F3 a){
    float n = sqrtf(dot3(a,a));
    float d = fmaxf(n, 1e-12f);
    return { a.x/d, a.y/d, a.z/d };
}
__device__ __forceinline__ F3 ld3(const float* p){ return { p[0], p[1], p[2] }; }
__device__ __forceinline__ float sgnf(float x){ return (x > 0.f) ? 1.f : ((x < 0.f) ? -1.f : 0.f); }

// packed f32x2 helpers
__device__ __forceinline__ unsigned long long pack2(float a, float b){
    unsigned long long r;
    asm("mov.b64 %0, {%1, %2};" : "=l"(r) : "f"(a), "f"(b));
    return r;
}
__device__ __forceinline__ void unpack2(unsigned long long v, float& a, float& b){
    asm("mov.b64 {%0, %1}, %2;" : "=f"(a), "=f"(b) : "l"(v));
}
__device__ __forceinline__ void pfma(unsigned long long& acc, unsigned long long a, unsigned long long b){
    asm("fma.rn.f32x2 %0, %1, %2, %0;" : "+l"(acc) : "l"(a), "l"(b));
}

// xyz layout: [B][L][6][3] row-major
__device__ __forceinline__ const float* atom_ptr(const float* xyz, int b, int l, int a){
    return xyz + (((size_t)(b*Lc + l))*6 + a)*3;
}
// chain point P(t) for X3 = xyz[:,:,:3] flattened to (3L,3)
__device__ __forceinline__ F3 ldP(const float* xyz, int b, int t){
    int r = t / 3, a = t - 3*r;
    return ld3(atom_ptr(xyz, b, r, a));
}

// ---------------------------------------------------------------------------
// prep: per-residue orientation frames O (padded) + last index per batch
// ---------------------------------------------------------------------------
__global__ void prep_kernel(const float* __restrict__ xyz, const float* __restrict__ mask){
    int gid = blockIdx.x*blockDim.x + threadIdx.x;
    if (gid < Bc){
        float s = 0.f;
        for (int j = 0; j < Lc; j++) s += mask[gid*Lc + j];
        g_last[gid] = (int)s - 1;
    }
    if (gid < Bc*Lc){
        int b = gid / Lc, l = gid % Lc;
        float o[9] = {0,0,0,0,0,0,0,0,0};
        if (l >= 1 && l <= Lc-3){
            F3 cm = ld3(atom_ptr(xyz,b,l-1,1));
            F3 c0 = ld3(atom_ptr(xyz,b,l  ,1));
            F3 cp = ld3(atom_ptr(xyz,b,l+1,1));
            F3 u2 = norm3v(f3sub(c0,cm));
            F3 u1 = norm3v(f3sub(cp,c0));
            F3 o1 = norm3v(f3sub(u2,u1));
            F3 n2 = norm3v(cross3(u2,u1));
            F3 o3 = cross3(o1,n2);
            o[0]=o1.x; o[1]=o1.y; o[2]=o1.z;
            o[3]=n2.x; o[4]=n2.y; o[5]=n2.z;
            o[6]=o3.x; o[7]=o3.y; o[8]=o3.z;
        }
        #pragma unroll
        for (int q = 0; q < 9; q++) g_O[(size_t)gid*9 + q] = o[q];
    }
}

// ---------------------------------------------------------------------------
// KNN: exact top-K ascending distance, tie -> lower index (matches lax.top_k)
// ---------------------------------------------------------------------------
__global__ void knn_kernel(const float* __restrict__ xyz, const float* __restrict__ mask,
                           float* __restrict__ out_eidx){
    __shared__ __align__(16) float sca[Lc*3];
    __shared__ float sd[Lc];
    __shared__ float sm[Lc];
    __shared__ float rv[8];
    __shared__ int   ri[8];
    __shared__ float s_dmax;

    int i = blockIdx.x, b = blockIdx.y, tid = threadIdx.x;

    for (int j = tid; j < Lc; j += 256){
        const float* p = atom_ptr(xyz, b, j, 1);
        sca[j*3+0] = p[0]; sca[j*3+1] = p[1]; sca[j*3+2] = p[2];
        sm[j] = mask[b*Lc + j];
    }
    __syncthreads();

    float xi = sca[i*3], yi = sca[i*3+1], zi = sca[i*3+2];
    float mi = sm[i];

    float dmax = -1e30f;
    for (int j = tid; j < Lc; j += 256){
        float dx = __fadd_rn(sca[j*3+0], -xi);
        float dy = __fadd_rn(sca[j*3+1], -yi);
        float dz = __fadd_rn(sca[j*3+2], -zi);
        float s  = __fadd_rn(__fadd_rn(__fmul_rn(dx,dx), __fmul_rn(dy,dy)), __fmul_rn(dz,dz));
        float D  = __fmul_rn(__fmul_rn(sm[j], mi), __fsqrt_rn(__fadd_rn(s, 1e-6f)));
        sd[j] = D;
        dmax = fmaxf(dmax, D);
    }
    #pragma unroll
    for (int o = 16; o; o >>= 1) dmax = fmaxf(dmax, __shfl_xor_sync(0xffffffffu, dmax, o));
    if ((tid & 31) == 0) rv[tid >> 5] = dmax;
    __syncthreads();
    if (tid == 0){
        float m = rv[0];
        #pragma unroll
        for (int w = 1; w < 8; w++) m = fmaxf(m, rv[w]);
        s_dmax = m;
    }
    __syncthreads();
    float Dmax = s_dmax;
    for (int j = tid; j < Lc; j += 256){
        float m2 = __fmul_rn(sm[j], mi);
        sd[j] = __fadd_rn(sd[j], __fmul_rn(__fadd_rn(1.0f, -m2), Dmax));
    }
    __syncthreads();

    size_t obase = (size_t)(b*Lc + i)*Kc;
    for (int it = 0; it < Kc; it++){
        float v = 1e38f; int idx = Lc;
        for (int j = tid; j < Lc; j += 256){
            float d = sd[j];
            if (d < v || (d == v && j < idx)){ v = d; idx = j; }
        }
        #pragma unroll
        for (int o = 16; o; o >>= 1){
            float v2 = __shfl_xor_sync(0xffffffffu, v, o);
            int   i2 = __shfl_xor_sync(0xffffffffu, idx, o);
            if (v2 < v || (v2 == v && i2 < idx)){ v = v2; idx = i2; }
        }
        if ((tid & 31) == 0){ rv[tid >> 5] = v; ri[tid >> 5] = idx; }
        __syncthreads();
        if (tid == 0){
            float bv = rv[0]; int bi = ri[0];
            #pragma unroll
            for (int w = 1; w < 8; w++){
                if (rv[w] < bv || (rv[w] == bv && ri[w] < bi)){ bv = rv[w]; bi = ri[w]; }
            }
            sd[bi] = 1e38f;
            g_eidx[obase + it] = bi;
            out_eidx[obase + it] = (float)bi;
        }
        __syncthreads();
    }
}

// ---------------------------------------------------------------------------
// Node: features (267) -> GEMM(267x128) -> LN.  4 rows per block, 128 threads.
// ---------------------------------------------------------------------------
__global__ void node_kernel(const float* __restrict__ xyz,
                            const float* __restrict__ nw, const float* __restrict__ nb,
                            const float* __restrict__ lg, const float* __restrict__ lb,
                            float* __restrict__ out){
    __shared__ __align__(16) float ft[NFN*4];
    __shared__ float outs[4][Hc+1];
    __shared__ float smu[4], srs[4];

    int tid = threadIdx.x;
    int warp = tid >> 5, lane = tid & 31;
    int gid = blockIdx.x*4 + warp;
    int b = gid / Lc, l = gid % Lc;

    // per-warp feature computation for row `warp`
    {
        const float* ap = xyz + (size_t)gid*18;
        F3 A0 = ld3(ap+0), A1 = ld3(ap+3), A2 = ld3(ap+6);
        F3 A3 = ld3(ap+9), A4 = ld3(ap+12), A5 = ld3(ap+15);
        F3 u = norm3v(f3sub(A0,A1));
        F3 v = norm3v(f3sub(A1,A2));
        F3 fb = norm3v(f3sub(u,v));
        F3 fn = norm3v(cross3(u,v));
        F3 fc = cross3(fb,fn);

        if (lane < 15){
            // node_dir
            const int sel[5] = {0,2,3,4,5};
            int a = lane/3, d = lane%3;
            F3 Aa = (sel[a]==0)?A0:((sel[a]==2)?A2:((sel[a]==3)?A3:((sel[a]==4)?A4:A5)));
            F3 t = norm3v(f3sub(Aa, A1));
            F3 col = (d==0)?fb:((d==1)?fn:fc);
            ft[lane*4 + warp] = dot3(t, col);

            // node_rbf: pair `lane`
            const int r0[15] = {0,0,0,0,0,1,1,1,1,2,2,2,3,3,4};
            const int r1[15] = {1,2,3,4,5,2,3,4,5,3,4,5,4,5,5};
            F3 P[6] = {A0,A1,A2,A3,A4,A5};
            F3 dd = f3sub(P[r0[lane]], P[r1[lane]]);
            float Dn = sqrtf(dot3(dd,dd));
            #pragma unroll
            for (int q = 0; q < RBFN; q++){
                float t2 = (Dn - (float)q*(20.0f/15.0f)) * 0.8f;
                ft[(27 + lane*RBFN + q)*4 + warp] = __expf(-t2*t2);
            }
        } else if (lane < 18){
            // angles, slot s
            int s = lane - 15;
            int p = 3*l + s;
            float Dd = 0.f, Db = 0.f;
            if (p >= 1 && p <= 3*Lc - 3){
                int raw = p - 1;
                F3 P0 = ldP(xyz,b,raw),   P1 = ldP(xyz,b,raw+1);
                F3 P2 = ldP(xyz,b,raw+2), P3 = ldP(xyz,b,raw+3);
                F3 u2 = norm3v(f3sub(P1,P0));
                F3 u1 = norm3v(f3sub(P2,P1));
                F3 u0 = norm3v(f3sub(P3,P2));
                F3 n2 = norm3v(cross3(u2,u1));
                F3 n1 = norm3v(cross3(u1,u0));
                float cd = fminf(fmaxf(dot3(n2,n1), -1.f + 1e-7f), 1.f - 1e-7f);
                Dd = sgnf(dot3(u2,n1)) * acosf(cd);
                float cb = fminf(fmaxf(dot3(u2,u1), -1.f + 1e-7f), 1.f - 1e-7f);
                Db = acosf(cb);
            }
            float cDd = cosf(Dd), sDd = sinf(Dd), cDb = cosf(Db), sDb = sinf(Db);
            if (l == g_last[b]){ cDd = 0.f; sDd = 0.f; cDb = 0.f; sDb = 0.f; }
            ft[(15 + s)*4 + warp] = cDd;
            ft[(18 + s)*4 + warp] = sDd;
            ft[(21 + s)*4 + warp] = cDb;
            ft[(24 + s)*4 + warp] = sDb;
        }
    }
    __syncthreads();

    // GEMM: thread = column h, rows packed in pairs via f32x2
    int h = tid;
    float bias = nb[h];
    unsigned long long acc0 = pack2(bias, bias);
    unsigned long long acc1 = pack2(bias, bias);
    for (int f = 0; f < NFN; f++){
        float wf = __ldg(nw + f*Hc + h);
        unsigned long long w2 = pack2(wf, wf);
        unsigned long long a0 = *reinterpret_cast<const unsigned long long*>(&ft[f*4 + 0]);
        unsigned long long a1 = *reinterpret_cast<const unsigned long long*>(&ft[f*4 + 2]);
        pfma(acc0, a0, w2);
        pfma(acc1, a1, w2);
    }
    float y0,y1,y2,y3;
    unpack2(acc0, y0, y1);
    unpack2(acc1, y2, y3);
    outs[0][h] = y0; outs[1][h] = y1; outs[2][h] = y2; outs[3][h] = y3;
    __syncthreads();

    if (tid < 4){
        float s = 0.f;
        for (int q = 0; q < Hc; q++) s += outs[tid][q];
        float mu = s / (float)Hc;
        float s2 = 0.f;
        for (int q = 0; q < Hc; q++){ float d = outs[tid][q] - mu; s2 += d*d; }
        smu[tid] = mu;
        srs[tid] = 1.f / sqrtf(s2 / (float)Hc + 1e-5f);
    }
    __syncthreads();

    int row0 = blockIdx.x*4;
    float gh = lg[h], bh = lb[h];
    #pragma unroll
    for (int r = 0; r < 4; r++){
        out[(size_t)(row0 + r)*Hc + h] = (outs[r][h] - smu[r])*srs[r]*gh + bh;
    }
}

// ---------------------------------------------------------------------------
// Edge: per (b,l): 30 neighbors x 121 features -> GEMM(121x128) -> LN
// ---------------------------------------------------------------------------
__global__ void edge_kernel(const float* __restrict__ xyz,
                            const float* __restrict__ ew, const float* __restrict__ eb,
                            const float* __restrict__ lg, const float* __restrict__ lb,
                            float* __restrict__ out){
    __shared__ __align__(16) float ftT[NFE*32];
    __shared__ float outs[Kc][Hc+1];
    __shared__ int   sjn[Kc];
    __shared__ float smu[Kc], srs[Kc];

    int l = blockIdx.x, b = blockIdx.y, tid = threadIdx.x;
    int base = b*Lc + l;

    if (tid < Kc) sjn[tid] = g_eidx[(size_t)base*Kc + tid];
    __syncthreads();

    if (tid < 120){
        int k = tid >> 2, sub = tid & 3;
        int j = sjn[k];
        const float* api = xyz + (size_t)base*18;
        const float* apj = xyz + (size_t)(b*Lc + j)*18;
        F3 Ca = ld3(api + 3);   // atom 1 of i

        if (sub <= 1){
            // frame of residue i
            F3 Ai0 = ld3(api+0), Ai2 = ld3(api+6);
            F3 u = norm3v(f3sub(Ai0, Ca));
            F3 v = norm3v(f3sub(Ca, Ai2));
            F3 fb = norm3v(f3sub(u,v));
            F3 fn = norm3v(cross3(u,v));
            F3 fc = cross3(fb,fn);
            int a0 = sub*3;
            #pragma unroll
            for (int a = a0; a < a0+3; a++){
                F3 t = norm3v(f3sub(ld3(apj + a*3), Ca));
                ftT[(a*3+0)*32 + k] = dot3(t, fb);
                ftT[(a*3+1)*32 + k] = dot3(t, fn);
                ftT[(a*3+2)*32 + k] = dot3(t, fc);
            }
            // rbf atom = sub
            {
                int a = sub;
                F3 d = f3sub(ld3(apj + a*3), Ca);
                float De = sqrtf(dot3(d,d));
                #pragma unroll
                for (int q = 0; q < RBFN; q++){
                    float t2 = (De - (float)q*(20.0f/15.0f))*0.8f;
                    ftT[(25 + a*RBFN + q)*32 + k] = __expf(-t2*t2);
                }
            }
        } else if (sub == 2){
            // orientation features
            float Om[9], On[9];
            #pragma unroll
            for (int q = 0; q < 9; q++) Om[q] = g_O[(size_t)base*9 + q];
            #pragma unroll
            for (int q = 0; q < 9; q++) On[q] = g_O[(size_t)(b*Lc + j)*9 + q];
            F3 Cj = ld3(apj + 3);
            F3 dX = f3sub(Cj, Ca);
            float d0 = Om[0]*dX.x + Om[1]*dX.y + Om[2]*dX.z;
            float d1 = Om[3]*dX.x + Om[4]*dX.y + Om[5]*dX.z;
            float d2 = Om[6]*dX.x + Om[7]*dX.y + Om[8]*dX.z;
            float nn = sqrtf(d0*d0 + d1*d1 + d2*d2);
            float inv = 1.f / fmaxf(nn, 1e-12f);
            ftT[18*32 + k] = d0*inv;
            ftT[19*32 + k] = d1*inv;
            ftT[20*32 + k] = d2*inv;
            // R = Om^T * On
            float R[3][3];
            #pragma unroll
            for (int ii = 0; ii < 3; ii++)
                #pragma unroll
                for (int m = 0; m < 3; m++)
                    R[ii][m] = Om[0*3+ii]*On[0*3+m] + Om[1*3+ii]*On[1*3+m] + Om[2*3+ii]*On[2*3+m];
            float Rxx = R[0][0], Ryy = R[1][1], Rzz = R[2][2];
            float mx = 0.5f*sqrtf(fabsf(1.f + Rxx - Ryy - Rzz));
            float my = 0.5f*sqrtf(fabsf(1.f - Rxx + Ryy - Rzz));
            float mz = 0.5f*sqrtf(fabsf(1.f - Rxx - Ryy + Rzz));
            float qx = sgnf(R[2][1] - R[1][2]) * mx;
            float qy = sgnf(R[0][2] - R[2][0]) * my;
            float qz = sgnf(R[1][0] - R[0][1]) * mz;
            float qw = sqrtf(fmaxf(1.f + Rxx + Ryy + Rzz, 0.f)) * 0.5f;
            float qn = sqrtf(qx*qx + qy*qy + qz*qz + qw*qw);
            float qi = 1.f / fmaxf(qn, 1e-12f);
            ftT[21*32 + k] = qx*qi;
            ftT[22*32 + k] = qy*qi;
            ftT[23*32 + k] = qz*qi;
            ftT[24*32 + k] = qw*qi;
            // rbf atoms 2,3
            #pragma unroll
            for (int a = 2; a <= 3; a++){
                F3 d = f3sub(ld3(apj + a*3), Ca);
                float De = sqrtf(dot3(d,d));
                #pragma unroll
                for (int q = 0; q < RBFN; q++){
                    float t2 = (De - (float)q*(20.0f/15.0f))*0.8f;
                    ftT[(25 + a*RBFN + q)*32 + k] = __expf(-t2*t2);
                }
            }
        } else {
            // rbf atoms 4,5
            #pragma unroll
            for (int a = 4; a <= 5; a++){
                F3 d = f3sub(ld3(apj + a*3), Ca);
                float De = sqrtf(dot3(d,d));
                #pragma unroll
                for (int q = 0; q < RBFN; q++){
                    float t2 = (De - (float)q*(20.0f/15.0f))*0.8f;
                    ftT[(25 + a*RBFN + q)*32 + k] = __expf(-t2*t2);
                }
            }
        }
    }
    __syncthreads();

    // GEMM: thread = column h; 30 rows as 15 f32x2 pairs
    int h = tid;
    float bias = eb[h];
    unsigned long long acc[15];
    #pragma unroll
    for (int p = 0; p < 15; p++) acc[p] = pack2(bias, bias);

    for (int f = 0; f < NFE; f++){
        float wf = __ldg(ew + f*Hc + h);
        unsigned long long w2 = pack2(wf, wf);
        const unsigned long long* row = reinterpret_cast<const unsigned long long*>(&ftT[f*32]);
        #pragma unroll
        for (int p = 0; p < 15; p++){
            pfma(acc[p], row[p], w2);
        }
    }
    #pragma unroll
    for (int p = 0; p < 15; p++){
        float a, bb2;
        unpack2(acc[p], a, bb2);
        outs[2*p  ][h] = a;
        outs[2*p+1][h] = bb2;
    }
    __syncthreads();

    if (tid < Kc){
        float s = 0.f;
        for (int q = 0; q < Hc; q++) s += outs[tid][q];
        float mu = s / (float)Hc;
        float s2 = 0.f;
        for (int q = 0; q < Hc; q++){ float d = outs[tid][q] - mu; s2 += d*d; }
        smu[tid] = mu;
        srs[tid] = 1.f / sqrtf(s2 / (float)Hc + 1e-5f);
    }
    __syncthreads();

    float gh = lg[h], bh = lb[h];
    #pragma unroll 5
    for (int r = 0; r < Kc; r++){
        out[((size_t)base*Kc + r)*Hc + h] = (outs[r][h] - smu[r])*srs[r]*gh + bh;
    }
}

// ---------------------------------------------------------------------------
extern "C" void kernel_launch(void* const* d_in, const int* in_sizes, int n_in,
                              void* d_out, int out_size){
    const float* xyz    = (const float*)d_in[0];
    const float* mask   = (const float*)d_in[1];
    const float* node_w = (const float*)d_in[2];
    const float* node_b = (const float*)d_in[3];
    const float* edge_w = (const float*)d_in[4];
    const float* edge_b = (const float*)d_in[5];
    const float* ln_ng  = (const float*)d_in[6];
    const float* ln_nb  = (const float*)d_in[7];
    const float* ln_eg  = (const float*)d_in[8];
    const float* ln_eb  = (const float*)d_in[9];

    float* out = (float*)d_out;
    float* out_node = out;
    float* out_edge = out + (size_t)Bc*Lc*Hc;
    float* out_eidx = out_edge + (size_t)Bc*Lc*Kc*Hc;

    prep_kernel<<<(Bc*Lc + 255)/256, 256>>>(xyz, mask);
    knn_kernel<<<dim3(Lc, Bc), 256>>>(xyz, mask, out_eidx);
    node_kernel<<<(Bc*Lc)/4, 128>>>(xyz, node_w, node_b, ln_ng, ln_nb, out_node);
    edge_kernel<<<dim3(Lc, Bc), 128>>>(xyz, edge_w, edge_b, ln_eg, ln_eb, out_edge);
}

// round 2
// speedup vs baseline: 1.3707x; 1.3707x over previous
#include <cuda_runtime.h>

// Problem constants
#define Bc 2
#define Lc 2048
#define Kc 30
#define Hc 128
#define RBFN 16
#define NFN 267   // node features: 15 dir + 12 angle + 240 rbf
#define NFE 121   // edge features: 18 dir + 7 ori + 96 rbf
#define QPB 8     // knn queries per block (one per warp)

// Scratch (device globals: allocation-free rule)
__device__ int   g_eidx[Bc*Lc*Kc];
__device__ float g_O[Bc*Lc*9];
__device__ int   g_last[Bc];

struct F3 { float x, y, z; };
__device__ __forceinline__ F3 f3sub(F3 a, F3 b){ return {a.x-b.x, a.y-b.y, a.z-b.z}; }
__device__ __forceinline__ float dot3(F3 a, F3 b){ return a.x*b.x + a.y*b.y + a.z*b.z; }
__device__ __forceinline__ F3 cross3(F3 a, F3 b){
    return { a.y*b.z - a.z*b.y, a.z*b.x - a.x*b.z, a.x*b.y - a.y*b.x };
}
__device__ __forceinline__ F3 norm3v(F3 a){
    float n = sqrtf(dot3(a,a));
    float d = fmaxf(n, 1e-12f);
    return { a.x/d, a.y/d, a.z/d };
}
__device__ __forceinline__ F3 ld3(const float* p){ return { p[0], p[1], p[2] }; }
__device__ __forceinline__ float sgnf(float x){ return (x > 0.f) ? 1.f : ((x < 0.f) ? -1.f : 0.f); }

// packed f32x2 helpers
__device__ __forceinline__ unsigned long long pack2(float a, float b){
    unsigned long long r;
    asm("mov.b64 %0, {%1, %2};" : "=l"(r) : "f"(a), "f"(b));
    return r;
}
__device__ __forceinline__ void unpack2(unsigned long long v, float& a, float& b){
    asm("mov.b64 {%0, %1}, %2;" : "=f"(a), "=f"(b) : "l"(v));
}
__device__ __forceinline__ void pfma(unsigned long long& acc, unsigned long long a, unsigned long long b){
    asm("fma.rn.f32x2 %0, %1, %2, %0;" : "+l"(acc) : "l"(a), "l"(b));
}

// xyz layout: [B][L][6][3] row-major
__device__ __forceinline__ const float* atom_ptr(const float* xyz, int b, int l, int a){
    return xyz + (((size_t)(b*Lc + l))*6 + a)*3;
}
// chain point P(t) for X3 = xyz[:,:,:3] flattened to (3L,3)
__device__ __forceinline__ F3 ldP(const float* xyz, int b, int t){
    int r = t / 3, a = t - 3*r;
    return ld3(atom_ptr(xyz, b, r, a));
}

// ---------------------------------------------------------------------------
// prep: per-residue orientation frames O (padded) + last index per batch
// ---------------------------------------------------------------------------
__global__ void prep_kernel(const float* __restrict__ xyz, const float* __restrict__ mask){
    int gid = blockIdx.x*blockDim.x + threadIdx.x;
    if (gid < Bc){
        float s = 0.f;
        for (int j = 0; j < Lc; j++) s += mask[gid*Lc + j];
        g_last[gid] = (int)s - 1;
    }
    if (gid < Bc*Lc){
        int b = gid / Lc, l = gid % Lc;
        float o[9] = {0,0,0,0,0,0,0,0,0};
        if (l >= 1 && l <= Lc-3){
            F3 cm = ld3(atom_ptr(xyz,b,l-1,1));
            F3 c0 = ld3(atom_ptr(xyz,b,l  ,1));
            F3 cp = ld3(atom_ptr(xyz,b,l+1,1));
            F3 u2 = norm3v(f3sub(c0,cm));
            F3 u1 = norm3v(f3sub(cp,c0));
            F3 o1 = norm3v(f3sub(u2,u1));
            F3 n2 = norm3v(cross3(u2,u1));
            F3 o3 = cross3(o1,n2);
            o[0]=o1.x; o[1]=o1.y; o[2]=o1.z;
            o[3]=n2.x; o[4]=n2.y; o[5]=n2.z;
            o[6]=o3.x; o[7]=o3.y; o[8]=o3.z;
        }
        #pragma unroll
        for (int q = 0; q < 9; q++) g_O[(size_t)gid*9 + q] = o[q];
    }
}

// ---------------------------------------------------------------------------
// KNN: one warp per query. Exact top-K ascending distance, tie -> lower index.
// Lane owns 64 candidates (stride 32); per-iteration: u64 packed shuffle-min
// + winner-lane rescan. No __syncthreads in the selection loop.
// ---------------------------------------------------------------------------
__global__ void __launch_bounds__(256) knn_kernel(const float* __restrict__ xyz,
                                                  const float* __restrict__ mask,
                                                  float* __restrict__ out_eidx){
    extern __shared__ float dyns[];
    float* sca = dyns;              // 3*Lc
    float* smk = sca + 3*Lc;        // Lc
    float* sdall = smk + Lc;        // QPB*Lc

    int tid = threadIdx.x;
    int w = tid >> 5, lane = tid & 31;
    int b = blockIdx.y;
    int i = blockIdx.x*QPB + w;

    for (int j = tid; j < Lc; j += 256){
        const float* p = atom_ptr(xyz, b, j, 1);
        sca[j*3+0] = p[0]; sca[j*3+1] = p[1]; sca[j*3+2] = p[2];
        smk[j] = mask[b*Lc + j];
    }
    __syncthreads();

    float* sdr = sdall + w*Lc;
    float xi = sca[i*3], yi = sca[i*3+1], zi = sca[i*3+2];
    float mi = smk[i];

    // distance pass + row max
    float dmax = -1e30f;
    #pragma unroll 4
    for (int m = 0; m < 64; m++){
        int j = lane + 32*m;
        float dx = __fadd_rn(sca[j*3+0], -xi);
        float dy = __fadd_rn(sca[j*3+1], -yi);
        float dz = __fadd_rn(sca[j*3+2], -zi);
        float s  = __fadd_rn(__fadd_rn(__fmul_rn(dx,dx), __fmul_rn(dy,dy)), __fmul_rn(dz,dz));
        float D  = __fmul_rn(__fmul_rn(smk[j], mi), __fsqrt_rn(__fadd_rn(s, 1e-6f)));
        sdr[j] = D;
        dmax = fmaxf(dmax, D);
    }
    #pragma unroll
    for (int o = 16; o; o >>= 1) dmax = fmaxf(dmax, __shfl_xor_sync(0xffffffffu, dmax, o));

    // mask adjust: Dadj = D + (1-m2)*Dmax
    #pragma unroll 4
    for (int m = 0; m < 64; m++){
        int j = lane + 32*m;
        float m2 = __fmul_rn(smk[j], mi);
        sdr[j] = __fadd_rn(sdr[j], __fmul_rn(__fadd_rn(1.0f, -m2), dmax));
    }
    // no sync needed: each lane reads only what it wrote

    // lane-local min over its 64 (ascending j + strict < => lowest idx on tie)
    float v = 1e38f; int vi = 0x7fffffff;
    #pragma unroll 8
    for (int m = 0; m < 64; m++){
        int j = lane + 32*m;
        float d = sdr[j];
        if (d < v){ v = d; vi = j; }
    }

    size_t obase = (size_t)(b*Lc + i)*Kc;
    for (int it = 0; it < Kc; it++){
        unsigned long long mykey = ((unsigned long long)__float_as_uint(v) << 32) | (unsigned)vi;
        unsigned long long kmin = mykey;
        #pragma unroll
        for (int o = 16; o; o >>= 1){
            unsigned long long o2 = __shfl_xor_sync(0xffffffffu, kmin, o);
            kmin = (o2 < kmin) ? o2 : kmin;
        }
        if (lane == 0){
            int bi = (int)(unsigned)kmin;
            g_eidx[obase + it] = bi;
            out_eidx[obase + it] = (float)bi;
        }
        if (mykey == kmin){
            sdr[vi] = 1e38f;
            v = 1e38f; vi = 0x7fffffff;
            #pragma unroll 8
            for (int m = 0; m < 64; m++){
                int j = lane + 32*m;
                float d = sdr[j];
                if (d < v){ v = d; vi = j; }
            }
        }
    }
}

// ---------------------------------------------------------------------------
// Node: features (267) -> GEMM(267x128) -> LN.  4 rows per block, 128 threads.
// ---------------------------------------------------------------------------
__global__ void __launch_bounds__(128) node_kernel(const float* __restrict__ xyz,
                            const float* __restrict__ nw, const float* __restrict__ nb,
                            const float* __restrict__ lg, const float* __restrict__ lb,
                            float* __restrict__ out){
    __shared__ __align__(16) float ft[NFN*4];
    __shared__ float outs[4][Hc+1];
    __shared__ float smu[4], srs[4];

    int tid = threadIdx.x;
    int warp = tid >> 5, lane = tid & 31;
    int gid = blockIdx.x*4 + warp;
    int b = gid / Lc, l = gid % Lc;

    // per-warp feature computation for row `warp`
    {
        const float* ap = xyz + (size_t)gid*18;
        F3 A0 = ld3(ap+0), A1 = ld3(ap+3), A2 = ld3(ap+6);
        F3 A3 = ld3(ap+9), A4 = ld3(ap+12), A5 = ld3(ap+15);
        F3 u = norm3v(f3sub(A0,A1));
        F3 v = norm3v(f3sub(A1,A2));
        F3 fb = norm3v(f3sub(u,v));
        F3 fn = norm3v(cross3(u,v));
        F3 fc = cross3(fb,fn);

        if (lane < 15){
            // node_dir
            const int sel[5] = {0,2,3,4,5};
            int a = lane/3, d = lane%3;
            F3 Aa = (sel[a]==0)?A0:((sel[a]==2)?A2:((sel[a]==3)?A3:((sel[a]==4)?A4:A5)));
            F3 t = norm3v(f3sub(Aa, A1));
            F3 col = (d==0)?fb:((d==1)?fn:fc);
            ft[lane*4 + warp] = dot3(t, col);

            // node_rbf: pair `lane`
            const int r0[15] = {0,0,0,0,0,1,1,1,1,2,2,2,3,3,4};
            const int r1[15] = {1,2,3,4,5,2,3,4,5,3,4,5,4,5,5};
            F3 P[6] = {A0,A1,A2,A3,A4,A5};
            F3 dd = f3sub(P[r0[lane]], P[r1[lane]]);
            float Dn = sqrtf(dot3(dd,dd));
            #pragma unroll
            for (int q = 0; q < RBFN; q++){
                float t2 = (Dn - (float)q*(20.0f/15.0f)) * 0.8f;
                ft[(27 + lane*RBFN + q)*4 + warp] = __expf(-t2*t2);
            }
        } else if (lane < 18){
            // angles, slot s
            int s = lane - 15;
            int p = 3*l + s;
            float Dd = 0.f, Db = 0.f;
            if (p >= 1 && p <= 3*Lc - 3){
                int raw = p - 1;
                F3 P0 = ldP(xyz,b,raw),   P1 = ldP(xyz,b,raw+1);
                F3 P2 = ldP(xyz,b,raw+2), P3 = ldP(xyz,b,raw+3);
                F3 u2 = norm3v(f3sub(P1,P0));
                F3 u1 = norm3v(f3sub(P2,P1));
                F3 u0 = norm3v(f3sub(P3,P2));
                F3 n2 = norm3v(cross3(u2,u1));
                F3 n1 = norm3v(cross3(u1,u0));
                float cd = fminf(fmaxf(dot3(n2,n1), -1.f + 1e-7f), 1.f - 1e-7f);
                Dd = sgnf(dot3(u2,n1)) * acosf(cd);
                float cb = fminf(fmaxf(dot3(u2,u1), -1.f + 1e-7f), 1.f - 1e-7f);
                Db = acosf(cb);
            }
            float cDd = cosf(Dd), sDd = sinf(Dd), cDb = cosf(Db), sDb = sinf(Db);
            if (l == g_last[b]){ cDd = 0.f; sDd = 0.f; cDb = 0.f; sDb = 0.f; }
            ft[(15 + s)*4 + warp] = cDd;
            ft[(18 + s)*4 + warp] = sDd;
            ft[(21 + s)*4 + warp] = cDb;
            ft[(24 + s)*4 + warp] = sDb;
        }
    }
    __syncthreads();

    // GEMM: thread = column h, one LDS.128 per feature (4 rows)
    int h = tid;
    float bias = nb[h];
    unsigned long long acc0 = pack2(bias, bias);
    unsigned long long acc1 = pack2(bias, bias);
    const ulonglong2* ftu = reinterpret_cast<const ulonglong2*>(ft);
    for (int f = 0; f < NFN; f++){
        float wf = __ldg(nw + f*Hc + h);
        unsigned long long w2 = pack2(wf, wf);
        ulonglong2 a = ftu[f];
        pfma(acc0, a.x, w2);
        pfma(acc1, a.y, w2);
    }
    float y0,y1,y2,y3;
    unpack2(acc0, y0, y1);
    unpack2(acc1, y2, y3);
    outs[0][h] = y0; outs[1][h] = y1; outs[2][h] = y2; outs[3][h] = y3;
    __syncthreads();

    if (tid < 4){
        float s = 0.f;
        for (int q = 0; q < Hc; q++) s += outs[tid][q];
        float mu = s / (float)Hc;
        float s2 = 0.f;
        for (int q = 0; q < Hc; q++){ float d = outs[tid][q] - mu; s2 += d*d; }
        smu[tid] = mu;
        srs[tid] = 1.f / sqrtf(s2 / (float)Hc + 1e-5f);
    }
    __syncthreads();

    int row0 = blockIdx.x*4;
    float gh = lg[h], bh = lb[h];
    #pragma unroll
    for (int r = 0; r < 4; r++){
        out[(size_t)(row0 + r)*Hc + h] = (outs[r][h] - smu[r])*srs[r]*gh + bh;
    }
}

// ---------------------------------------------------------------------------
// Edge: per (b,l): 30 neighbors x 121 features -> GEMM(121x128) -> LN
// ---------------------------------------------------------------------------
__global__ void __launch_bounds__(128, 4) edge_kernel(const float* __restrict__ xyz,
                            const float* __restrict__ ew, const float* __restrict__ eb,
                            const float* __restrict__ lg, const float* __restrict__ lb,
                            float* __restrict__ out){
    __shared__ __align__(16) float ftT[NFE*32];
    __shared__ float outs[Kc][Hc+1];
    __shared__ int   sjn[Kc];
    __shared__ float smu[Kc], srs[Kc];

    int l = blockIdx.x, b = blockIdx.y, tid = threadIdx.x;
    int base = b*Lc + l;

    if (tid < Kc) sjn[tid] = g_eidx[(size_t)base*Kc + tid];
    __syncthreads();

    if (tid < 120){
        int k = tid >> 2, sub = tid & 3;
        int j = sjn[k];
        const float* api = xyz + (size_t)base*18;
        const float* apj = xyz + (size_t)(b*Lc + j)*18;
        F3 Ca = ld3(api + 3);   // atom 1 of i

        if (sub <= 1){
            // frame of residue i
            F3 Ai0 = ld3(api+0), Ai2 = ld3(api+6);
            F3 u = norm3v(f3sub(Ai0, Ca));
            F3 v = norm3v(f3sub(Ca, Ai2));
            F3 fb = norm3v(f3sub(u,v));
            F3 fn = norm3v(cross3(u,v));
            F3 fc = cross3(fb,fn);
            int a0 = sub*3;
            #pragma unroll
            for (int a = a0; a < a0+3; a++){
                F3 t = norm3v(f3sub(ld3(apj + a*3), Ca));
                ftT[(a*3+0)*32 + k] = dot3(t, fb);
                ftT[(a*3+1)*32 + k] = dot3(t, fn);
                ftT[(a*3+2)*32 + k] = dot3(t, fc);
            }
            // rbf atom = sub
            {
                int a = sub;
                F3 d = f3sub(ld3(apj + a*3), Ca);
                float De = sqrtf(dot3(d,d));
                #pragma unroll
                for (int q = 0; q < RBFN; q++){
                    float t2 = (De - (float)q*(20.0f/15.0f))*0.8f;
                    ftT[(25 + a*RBFN + q)*32 + k] = __expf(-t2*t2);
                }
            }
        } else if (sub == 2){
            // orientation features
            float Om[9], On[9];
            #pragma unroll
            for (int q = 0; q < 9; q++) Om[q] = g_O[(size_t)base*9 + q];
            #pragma unroll
            for (int q = 0; q < 9; q++) On[q] = g_O[(size_t)(b*Lc + j)*9 + q];
            F3 Cj = ld3(apj + 3);
            F3 dX = f3sub(Cj, Ca);
            float d0 = Om[0]*dX.x + Om[1]*dX.y + Om[2]*dX.z;
            float d1 = Om[3]*dX.x + Om[4]*dX.y + Om[5]*dX.z;
            float d2 = Om[6]*dX.x + Om[7]*dX.y + Om[8]*dX.z;
            float nn = sqrtf(d0*d0 + d1*d1 + d2*d2);
            float inv = 1.f / fmaxf(nn, 1e-12f);
            ftT[18*32 + k] = d0*inv;
            ftT[19*32 + k] = d1*inv;
            ftT[20*32 + k] = d2*inv;
            // R = Om^T * On
            float R[3][3];
            #pragma unroll
            for (int ii = 0; ii < 3; ii++)
                #pragma unroll
                for (int m = 0; m < 3; m++)
                    R[ii][m] = Om[0*3+ii]*On[0*3+m] + Om[1*3+ii]*On[1*3+m] + Om[2*3+ii]*On[2*3+m];
            float Rxx = R[0][0], Ryy = R[1][1], Rzz = R[2][2];
            float mx = 0.5f*sqrtf(fabsf(1.f + Rxx - Ryy - Rzz));
            float my = 0.5f*sqrtf(fabsf(1.f - Rxx + Ryy - Rzz));
            float mz = 0.5f*sqrtf(fabsf(1.f - Rxx - Ryy + Rzz));
            float qx = sgnf(R[2][1] - R[1][2]) * mx;
            float qy = sgnf(R[0][2] - R[2][0]) * my;
            float qz = sgnf(R[1][0] - R[0][1]) * mz;
            float qw = sqrtf(fmaxf(1.f + Rxx + Ryy + Rzz, 0.f)) * 0.5f;
            float qn = sqrtf(qx*qx + qy*qy + qz*qz + qw*qw);
            float qi = 1.f / fmaxf(qn, 1e-12f);
            ftT[21*32 + k] = qx*qi;
            ftT[22*32 + k] = qy*qi;
            ftT[23*32 + k] = qz*qi;
            ftT[24*32 + k] = qw*qi;
            // rbf atoms 2,3
            #pragma unroll
            for (int a = 2; a <= 3; a++){
                F3 d = f3sub(ld3(apj + a*3), Ca);
                float De = sqrtf(dot3(d,d));
                #pragma unroll
                for (int q = 0; q < RBFN; q++){
                    float t2 = (De - (float)q*(20.0f/15.0f))*0.8f;
                    ftT[(25 + a*RBFN + q)*32 + k] = __expf(-t2*t2);
                }
            }
        } else {
            // rbf atoms 4,5
            #pragma unroll
            for (int a = 4; a <= 5; a++){
                F3 d = f3sub(ld3(apj + a*3), Ca);
                float De = sqrtf(dot3(d,d));
                #pragma unroll
                for (int q = 0; q < RBFN; q++){
                    float t2 = (De - (float)q*(20.0f/15.0f))*0.8f;
                    ftT[(25 + a*RBFN + q)*32 + k] = __expf(-t2*t2);
                }
            }
        }
    }
    __syncthreads();

    // GEMM: thread = column h; 30 rows via 8 LDS.128 per feature
    int h = tid;
    float bias = eb[h];
    unsigned long long acc[15];
    #pragma unroll
    for (int p = 0; p < 15; p++) acc[p] = pack2(bias, bias);

    const ulonglong2* ftu = reinterpret_cast<const ulonglong2*>(ftT); // index f*8 + q
    for (int f = 0; f < NFE; f++){
        float wf = __ldg(ew + f*Hc + h);
        unsigned long long w2 = pack2(wf, wf);
        #pragma unroll
        for (int q = 0; q < 7; q++){
            ulonglong2 pr = ftu[f*8 + q];
            pfma(acc[2*q  ], pr.x, w2);
            pfma(acc[2*q+1], pr.y, w2);
        }
        ulonglong2 pr7 = ftu[f*8 + 7];
        pfma(acc[14], pr7.x, w2);
    }
    #pragma unroll
    for (int p = 0; p < 15; p++){
        float a, bb2;
        unpack2(acc[p], a, bb2);
        outs[2*p  ][h] = a;
        outs[2*p+1][h] = bb2;
    }
    __syncthreads();

    if (tid < Kc){
        float s = 0.f;
        for (int q = 0; q < Hc; q++) s += outs[tid][q];
        float mu = s / (float)Hc;
        float s2 = 0.f;
        for (int q = 0; q < Hc; q++){ float d = outs[tid][q] - mu; s2 += d*d; }
        smu[tid] = mu;
        srs[tid] = 1.f / sqrtf(s2 / (float)Hc + 1e-5f);
    }
    __syncthreads();

    float gh = lg[h], bh = lb[h];
    #pragma unroll 5
    for (int r = 0; r < Kc; r++){
        out[((size_t)base*Kc + r)*Hc + h] = (outs[r][h] - smu[r])*srs[r]*gh + bh;
    }
}

// ---------------------------------------------------------------------------
extern "C" void kernel_launch(void* const* d_in, const int* in_sizes, int n_in,
                              void* d_out, int out_size){
    const float* xyz    = (const float*)d_in[0];
    const float* mask   = (const float*)d_in[1];
    const float* node_w = (const float*)d_in[2];
    const float* node_b = (const float*)d_in[3];
    const float* edge_w = (const float*)d_in[4];
    const float* edge_b = (const float*)d_in[5];
    const float* ln_ng  = (const float*)d_in[6];
    const float* ln_nb  = (const float*)d_in[7];
    const float* ln_eg  = (const float*)d_in[8];
    const float* ln_eb  = (const float*)d_in[9];

    float* out = (float*)d_out;
    float* out_node = out;
    float* out_edge = out + (size_t)Bc*Lc*Hc;
    float* out_eidx = out_edge + (size_t)Bc*Lc*Kc*Hc;

    const int knn_smem = (3*Lc + Lc + QPB*Lc) * (int)sizeof(float); // 96 KB
    cudaFuncSetAttribute(knn_kernel, cudaFuncAttributeMaxDynamicSharedMemorySize, knn_smem);

    prep_kernel<<<(Bc*Lc + 255)/256, 256>>>(xyz, mask);
    knn_kernel<<<dim3(Lc/QPB, Bc), 256, knn_smem>>>(xyz, mask, out_eidx);
    node_kernel<<<(Bc*Lc)/4, 128>>>(xyz, node_w, node_b, ln_ng, ln_nb, out_node);
    edge_kernel<<<dim3(Lc, Bc), 128>>>(xyz, edge_w, edge_b, ln_eg, ln_eb, out_edge);
}

// round 3
// speedup vs baseline: 2.0160x; 1.4708x over previous
#include <cuda_runtime.h>

// Problem constants
#define Bc 2
#define Lc 2048
#define Kc 30
#define Hc 128
#define RBFN 16
#define NFN 267   // node features: 15 dir + 12 angle + 240 rbf
#define NFE 121   // edge features: 18 dir + 7 ori + 96 rbf
#define QPB 8     // knn queries per block (one per warp)

// Scratch (device globals: allocation-free rule)
__device__ int   g_eidx[Bc*Lc*Kc];
__device__ float g_O[Bc*Lc*9];
__device__ int   g_last[Bc];

struct F3 { float x, y, z; };
__device__ __forceinline__ F3 f3sub(F3 a, F3 b){ return {a.x-b.x, a.y-b.y, a.z-b.z}; }
__device__ __forceinline__ float dot3(F3 a, F3 b){ return a.x*b.x + a.y*b.y + a.z*b.z; }
__device__ __forceinline__ F3 cross3(F3 a, F3 b){
    return { a.y*b.z - a.z*b.y, a.z*b.x - a.x*b.z, a.x*b.y - a.y*b.x };
}
__device__ __forceinline__ F3 norm3v(F3 a){
    float n = sqrtf(dot3(a,a));
    float d = fmaxf(n, 1e-12f);
    return { a.x/d, a.y/d, a.z/d };
}
__device__ __forceinline__ F3 ld3(const float* p){ return { p[0], p[1], p[2] }; }
__device__ __forceinline__ float sgnf(float x){ return (x > 0.f) ? 1.f : ((x < 0.f) ? -1.f : 0.f); }

// packed f32x2 helpers
__device__ __forceinline__ unsigned long long pack2(float a, float b){
    unsigned long long r;
    asm("mov.b64 %0, {%1, %2};" : "=l"(r) : "f"(a), "f"(b));
    return r;
}
__device__ __forceinline__ void unpack2(unsigned long long v, float& a, float& b){
    asm("mov.b64 {%0, %1}, %2;" : "=f"(a), "=f"(b) : "l"(v));
}
__device__ __forceinline__ void pfma(unsigned long long& acc, unsigned long long a, unsigned long long b){
    asm("fma.rn.f32x2 %0, %1, %2, %0;" : "+l"(acc) : "l"(a), "l"(b));
}

// xyz layout: [B][L][6][3] row-major
__device__ __forceinline__ const float* atom_ptr(const float* xyz, int b, int l, int a){
    return xyz + (((size_t)(b*Lc + l))*6 + a)*3;
}
// chain point P(t) for X3 = xyz[:,:,:3] flattened to (3L,3)
__device__ __forceinline__ F3 ldP(const float* xyz, int b, int t){
    int r = t / 3, a = t - 3*r;
    return ld3(atom_ptr(xyz, b, r, a));
}

// ---------------------------------------------------------------------------
// prep: per-residue orientation frames O (padded) + last index per batch
// ---------------------------------------------------------------------------
__global__ void prep_kernel(const float* __restrict__ xyz, const float* __restrict__ mask){
    int gid = blockIdx.x*blockDim.x + threadIdx.x;
    if (blockIdx.x == 0 && threadIdx.x < 64){
        int b = threadIdx.x >> 5, lane = threadIdx.x & 31;
        float s = 0.f;
        for (int m = lane; m < Lc; m += 32) s += mask[b*Lc + m];
        #pragma unroll
        for (int o = 16; o; o >>= 1) s += __shfl_xor_sync(0xffffffffu, s, o);
        if (lane == 0) g_last[b] = (int)s - 1;
    }
    if (gid < Bc*Lc){
        int b = gid / Lc, l = gid % Lc;
        float o[9] = {0,0,0,0,0,0,0,0,0};
        if (l >= 1 && l <= Lc-3){
            F3 cm = ld3(atom_ptr(xyz,b,l-1,1));
            F3 c0 = ld3(atom_ptr(xyz,b,l  ,1));
            F3 cp = ld3(atom_ptr(xyz,b,l+1,1));
            F3 u2 = norm3v(f3sub(c0,cm));
            F3 u1 = norm3v(f3sub(cp,c0));
            F3 o1 = norm3v(f3sub(u2,u1));
            F3 n2 = norm3v(cross3(u2,u1));
            F3 o3 = cross3(o1,n2);
            o[0]=o1.x; o[1]=o1.y; o[2]=o1.z;
            o[3]=n2.x; o[4]=n2.y; o[5]=n2.z;
            o[6]=o3.x; o[7]=o3.y; o[8]=o3.z;
        }
        #pragma unroll
        for (int q = 0; q < 9; q++) g_O[(size_t)gid*9 + q] = o[q];
    }
}

// ---------------------------------------------------------------------------
// KNN: one warp per query. Exact top-K ascending distance, tie -> lower index.
// Per-lane top-3 in registers; selection via redux.sync (value, then index).
// ---------------------------------------------------------------------------
__device__ __forceinline__ void knn_insert3(float d, int j,
    float& v1, int& i1, float& v2, int& i2, float& v3, int& i3){
    if (d < v3){
        if (d < v2){
            if (d < v1){ v3=v2; i3=i2; v2=v1; i2=i1; v1=d; i1=j; }
            else       { v3=v2; i3=i2; v2=d;  i2=j; }
        } else         { v3=d;  i3=j; }
    }
}

__global__ void __launch_bounds__(256) knn_kernel(const float* __restrict__ xyz,
                                                  const float* __restrict__ mask,
                                                  float* __restrict__ out_eidx){
    extern __shared__ float dyns[];
    float* sca = dyns;              // 3*Lc
    float* smk = sca + 3*Lc;        // Lc
    float* sdall = smk + Lc;        // QPB*Lc

    int tid = threadIdx.x;
    int w = tid >> 5, lane = tid & 31;
    int b = blockIdx.y;
    int i = blockIdx.x*QPB + w;

    for (int j = tid; j < Lc; j += 256){
        const float* p = atom_ptr(xyz, b, j, 1);
        sca[j*3+0] = p[0]; sca[j*3+1] = p[1]; sca[j*3+2] = p[2];
        smk[j] = mask[b*Lc + j];
    }
    __syncthreads();

    float* sdr = sdall + w*Lc;
    float xi = sca[i*3], yi = sca[i*3+1], zi = sca[i*3+2];
    float mi = smk[i];

    // distance pass + row max
    float dmax = -1e30f;
    #pragma unroll 4
    for (int m = 0; m < 64; m++){
        int j = lane + 32*m;
        float dx = __fadd_rn(sca[j*3+0], -xi);
        float dy = __fadd_rn(sca[j*3+1], -yi);
        float dz = __fadd_rn(sca[j*3+2], -zi);
        float s  = __fadd_rn(__fadd_rn(__fmul_rn(dx,dx), __fmul_rn(dy,dy)), __fmul_rn(dz,dz));
        float D  = __fmul_rn(__fmul_rn(smk[j], mi), __fsqrt_rn(__fadd_rn(s, 1e-6f)));
        sdr[j] = D;
        dmax = fmaxf(dmax, D);
    }
    // all distances >= 0 -> float bits order == value order
    {
        unsigned mb = __reduce_max_sync(0xffffffffu, __float_as_uint(dmax));
        dmax = __uint_as_float(mb);
    }

    // mask adjust: Dadj = D + (1-m2)*Dmax, and build per-lane top-3
    float v1 = 1e38f, v2 = 1e38f, v3 = 1e38f;
    int   i1 = 0x7fffffff, i2 = 0x7fffffff, i3 = 0x7fffffff;
    #pragma unroll 4
    for (int m = 0; m < 64; m++){
        int j = lane + 32*m;
        float m2 = __fmul_rn(smk[j], mi);
        float d = __fadd_rn(sdr[j], __fmul_rn(__fadd_rn(1.0f, -m2), dmax));
        sdr[j] = d;
        knn_insert3(d, j, v1, i1, v2, i2, v3, i3);
    }

    size_t obase = (size_t)(b*Lc + i)*Kc;
    for (int it = 0; it < Kc; it++){
        unsigned myb = __float_as_uint(v1);
        unsigned kb = __reduce_min_sync(0xffffffffu, myb);
        unsigned cand = (myb == kb) ? (unsigned)i1 : 0xffffffffu;
        unsigned ib = __reduce_min_sync(0xffffffffu, cand);
        if (lane == 0){
            g_eidx[obase + it] = (int)ib;
            out_eidx[obase + it] = (float)ib;
        }
        if (myb == kb && (unsigned)i1 == ib){
            sdr[i1] = 1e38f;    // mark taken
            v1 = v2; i1 = i2;
            v2 = v3; i2 = i3;
            v3 = 1e38f; i3 = 0x7fffffff;
            if (v1 == 1e38f && it < Kc-1){
                // refill top-3 from remaining candidates
                v1 = v2 = v3 = 1e38f; i1 = i2 = i3 = 0x7fffffff;
                #pragma unroll 8
                for (int m = 0; m < 64; m++){
                    int j = lane + 32*m;
                    float d = sdr[j];
                    knn_insert3(d, j, v1, i1, v2, i2, v3, i3);
                }
            }
        }
    }
}

// ---------------------------------------------------------------------------
// Node: features (267) -> GEMM(267x128) -> LN.  4 rows per block, 128 threads.
// ---------------------------------------------------------------------------
__global__ void __launch_bounds__(128) node_kernel(const float* __restrict__ xyz,
                            const float* __restrict__ nw, const float* __restrict__ nb,
                            const float* __restrict__ lg, const float* __restrict__ lb,
                            float* __restrict__ out){
    __shared__ __align__(16) float ft[NFN*4];
    __shared__ float outs[4][Hc+1];
    __shared__ float smu[4], srs[4];

    int tid = threadIdx.x;
    int warp = tid >> 5, lane = tid & 31;
    int gid = blockIdx.x*4 + warp;
    int b = gid / Lc, l = gid % Lc;

    // per-warp feature computation for row `warp`
    {
        const float* ap = xyz + (size_t)gid*18;
        F3 A0 = ld3(ap+0), A1 = ld3(ap+3), A2 = ld3(ap+6);
        F3 A3 = ld3(ap+9), A4 = ld3(ap+12), A5 = ld3(ap+15);
        F3 u = norm3v(f3sub(A0,A1));
        F3 v = norm3v(f3sub(A1,A2));
        F3 fb = norm3v(f3sub(u,v));
        F3 fn = norm3v(cross3(u,v));
        F3 fc = cross3(fb,fn);

        if (lane < 15){
            // node_dir
            const int sel[5] = {0,2,3,4,5};
            int a = lane/3, d = lane%3;
            F3 Aa = (sel[a]==0)?A0:((sel[a]==2)?A2:((sel[a]==3)?A3:((sel[a]==4)?A4:A5)));
            F3 t = norm3v(f3sub(Aa, A1));
            F3 col = (d==0)?fb:((d==1)?fn:fc);
            ft[lane*4 + warp] = dot3(t, col);

            // node_rbf: pair `lane`
            const int r0[15] = {0,0,0,0,0,1,1,1,1,2,2,2,3,3,4};
            const int r1[15] = {1,2,3,4,5,2,3,4,5,3,4,5,4,5,5};
            F3 P[6] = {A0,A1,A2,A3,A4,A5};
            F3 dd = f3sub(P[r0[lane]], P[r1[lane]]);
            float Dn = sqrtf(dot3(dd,dd));
            #pragma unroll
            for (int q = 0; q < RBFN; q++){
                float t2 = (Dn - (float)q*(20.0f/15.0f)) * 0.8f;
                ft[(27 + lane*RBFN + q)*4 + warp] = __expf(-t2*t2);
            }
        } else if (lane < 18){
            // angles, slot s
            int s = lane - 15;
            int p = 3*l + s;
            float Dd = 0.f, Db = 0.f;
            if (p >= 1 && p <= 3*Lc - 3){
                int raw = p - 1;
                F3 P0 = ldP(xyz,b,raw),   P1 = ldP(xyz,b,raw+1);
                F3 P2 = ldP(xyz,b,raw+2), P3 = ldP(xyz,b,raw+3);
                F3 u2 = norm3v(f3sub(P1,P0));
                F3 u1 = norm3v(f3sub(P2,P1));
                F3 u0 = norm3v(f3sub(P3,P2));
                F3 n2 = norm3v(cross3(u2,u1));
                F3 n1 = norm3v(cross3(u1,u0));
                float cd = fminf(fmaxf(dot3(n2,n1), -1.f + 1e-7f), 1.f - 1e-7f);
                Dd = sgnf(dot3(u2,n1)) * acosf(cd);
                float cb = fminf(fmaxf(dot3(u2,u1), -1.f + 1e-7f), 1.f - 1e-7f);
                Db = acosf(cb);
            }
            float cDd = cosf(Dd), sDd = sinf(Dd), cDb = cosf(Db), sDb = sinf(Db);
            if (l == g_last[b]){ cDd = 0.f; sDd = 0.f; cDb = 0.f; sDb = 0.f; }
            ft[(15 + s)*4 + warp] = cDd;
            ft[(18 + s)*4 + warp] = sDd;
            ft[(21 + s)*4 + warp] = cDb;
            ft[(24 + s)*4 + warp] = sDb;
        }
    }
    __syncthreads();

    // GEMM: thread = column h, one LDS.128 per feature (4 rows)
    int h = tid;
    float bias = nb[h];
    unsigned long long acc0 = pack2(bias, bias);
    unsigned long long acc1 = pack2(bias, bias);
    const ulonglong2* ftu = reinterpret_cast<const ulonglong2*>(ft);
    for (int f = 0; f < NFN; f++){
        float wf = __ldg(nw + f*Hc + h);
        unsigned long long w2 = pack2(wf, wf);
        ulonglong2 a = ftu[f];
        pfma(acc0, a.x, w2);
        pfma(acc1, a.y, w2);
    }
    float y0,y1,y2,y3;
    unpack2(acc0, y0, y1);
    unpack2(acc1, y2, y3);
    outs[0][h] = y0; outs[1][h] = y1; outs[2][h] = y2; outs[3][h] = y3;
    __syncthreads();

    if (tid < 4){
        float s = 0.f;
        for (int q = 0; q < Hc; q++) s += outs[tid][q];
        float mu = s / (float)Hc;
        float s2 = 0.f;
        for (int q = 0; q < Hc; q++){ float d = outs[tid][q] - mu; s2 += d*d; }
        smu[tid] = mu;
        srs[tid] = 1.f / sqrtf(s2 / (float)Hc + 1e-5f);
    }
    __syncthreads();

    int row0 = blockIdx.x*4;
    float gh = lg[h], bh = lb[h];
    #pragma unroll
    for (int r = 0; r < 4; r++){
        out[(size_t)(row0 + r)*Hc + h] = (outs[r][h] - smu[r])*srs[r]*gh + bh;
    }
}

// ---------------------------------------------------------------------------
// Edge: 2 tiles per 128-thread block; 64 threads/tile, 2 output columns/thread.
// Per (b,l): 30 neighbors x 121 features -> GEMM(121x128) -> LN
// ---------------------------------------------------------------------------
#define EDGE_SMEM_FLOATS (2*NFE*32 + 2*Kc*129 + 64 + 64 + 64)

__global__ void __launch_bounds__(128, 3) edge_kernel(const float* __restrict__ xyz,
                            const float* __restrict__ ew, const float* __restrict__ eb,
                            const float* __restrict__ lg, const float* __restrict__ lb,
                            float* __restrict__ out){
    extern __shared__ float es[];
    float* ftT  = es;                               // [2][NFE*32]
    float* outs = ftT + 2*NFE*32;                   // [2][Kc*129]
    int*   sjn  = (int*)(outs + 2*Kc*129);          // [2][32]
    float* smu  = (float*)(sjn + 64);               // [2][32]
    float* srs  = smu + 64;                         // [2][32]

    int tid = threadIdx.x;
    int tile = tid >> 6;
    int t = tid & 63;
    int l = blockIdx.x*2 + tile;
    int b = blockIdx.y;
    int base = b*Lc + l;

    float* ft = ftT + tile*(NFE*32);
    float* ou = outs + tile*(Kc*129);

    if (t < Kc) sjn[tile*32 + t] = g_eidx[(size_t)base*Kc + t];
    __syncthreads();

    if (t < 60){
        int k = t >> 1, sub = t & 1;
        int j = sjn[tile*32 + k];
        const float* api = xyz + (size_t)base*18;
        const float* apj = xyz + (size_t)(b*Lc + j)*18;
        F3 Ca = ld3(api + 3);   // atom 1 of i

        // frame of residue i (both subs compute it)
        F3 Ai0 = ld3(api+0), Ai2 = ld3(api+6);
        F3 u = norm3v(f3sub(Ai0, Ca));
        F3 v = norm3v(f3sub(Ca, Ai2));
        F3 fb = norm3v(f3sub(u,v));
        F3 fn = norm3v(cross3(u,v));
        F3 fc = cross3(fb,fn);

        if (sub == 0){
            // dir atoms 0..2 + rbf atoms 0..2
            #pragma unroll
            for (int a = 0; a < 3; a++){
                F3 tv = norm3v(f3sub(ld3(apj + a*3), Ca));
                ft[(a*3+0)*32 + k] = dot3(tv, fb);
                ft[(a*3+1)*32 + k] = dot3(tv, fn);
                ft[(a*3+2)*32 + k] = dot3(tv, fc);
            }
            #pragma unroll
            for (int a = 0; a < 3; a++){
                F3 d = f3sub(ld3(apj + a*3), Ca);
                float De = sqrtf(dot3(d,d));
                #pragma unroll
                for (int q = 0; q < RBFN; q++){
                    float t2 = (De - (float)q*(20.0f/15.0f))*0.8f;
                    ft[(25 + a*RBFN + q)*32 + k] = __expf(-t2*t2);
                }
            }
        } else {
            // dir atoms 3..5 + ori + rbf atoms 3..5
            #pragma unroll
            for (int a = 3; a < 6; a++){
                F3 tv = norm3v(f3sub(ld3(apj + a*3), Ca));
                ft[(a*3+0)*32 + k] = dot3(tv, fb);
                ft[(a*3+1)*32 + k] = dot3(tv, fn);
                ft[(a*3+2)*32 + k] = dot3(tv, fc);
            }
            // orientation features
            float Om[9], On[9];
            #pragma unroll
            for (int q = 0; q < 9; q++) Om[q] = g_O[(size_t)base*9 + q];
            #pragma unroll
            for (int q = 0; q < 9; q++) On[q] = g_O[(size_t)(b*Lc + j)*9 + q];
            F3 Cj = ld3(apj + 3);
            F3 dX = f3sub(Cj, Ca);
            float d0 = Om[0]*dX.x + Om[1]*dX.y + Om[2]*dX.z;
            float d1 = Om[3]*dX.x + Om[4]*dX.y + Om[5]*dX.z;
            float d2 = Om[6]*dX.x + Om[7]*dX.y + Om[8]*dX.z;
            float nn = sqrtf(d0*d0 + d1*d1 + d2*d2);
            float inv = 1.f / fmaxf(nn, 1e-12f);
            ft[18*32 + k] = d0*inv;
            ft[19*32 + k] = d1*inv;
            ft[20*32 + k] = d2*inv;
            // R = Om^T * On
            float R[3][3];
            #pragma unroll
            for (int ii = 0; ii < 3; ii++)
                #pragma unroll
                for (int m = 0; m < 3; m++)
                    R[ii][m] = Om[0*3+ii]*On[0*3+m] + Om[1*3+ii]*On[1*3+m] + Om[2*3+ii]*On[2*3+m];
            float Rxx = R[0][0], Ryy = R[1][1], Rzz = R[2][2];
            float mx = 0.5f*sqrtf(fabsf(1.f + Rxx - Ryy - Rzz));
            float my = 0.5f*sqrtf(fabsf(1.f - Rxx + Ryy - Rzz));
            float mz = 0.5f*sqrtf(fabsf(1.f - Rxx - Ryy + Rzz));
            float qx = sgnf(R[2][1] - R[1][2]) * mx;
            float qy = sgnf(R[0][2] - R[2][0]) * my;
            float qz = sgnf(R[1][0] - R[0][1]) * mz;
            float qw = sqrtf(fmaxf(1.f + Rxx + Ryy + Rzz, 0.f)) * 0.5f;
            float qn = sqrtf(qx*qx + qy*qy + qz*qz + qw*qw);
            float qi = 1.f / fmaxf(qn, 1e-12f);
            ft[21*32 + k] = qx*qi;
            ft[22*32 + k] = qy*qi;
            ft[23*32 + k] = qz*qi;
            ft[24*32 + k] = qw*qi;
            // rbf atoms 3..5
            #pragma unroll
            for (int a = 3; a < 6; a++){
                F3 d = f3sub(ld3(apj + a*3), Ca);
                float De = sqrtf(dot3(d,d));
                #pragma unroll
                for (int q = 0; q < RBFN; q++){
                    float t2 = (De - (float)q*(20.0f/15.0f))*0.8f;
                    ft[(25 + a*RBFN + q)*32 + k] = __expf(-t2*t2);
                }
            }
        }
    }
    __syncthreads();

    // GEMM: thread = columns (h0, h1); 30 rows via 8 LDS.128 per feature
    int h0 = t, h1 = t + 64;
    float b0 = eb[h0], b1 = eb[h1];
    unsigned long long acc0[15], acc1[15];
    #pragma unroll
    for (int p = 0; p < 15; p++){ acc0[p] = pack2(b0, b0); acc1[p] = pack2(b1, b1); }

    const ulonglong2* ftu = reinterpret_cast<const ulonglong2*>(ft); // index f*8 + q
    #pragma unroll 2
    for (int f = 0; f < NFE; f++){
        float w0 = __ldg(ew + f*Hc + h0);
        float w1 = __ldg(ew + f*Hc + h1);
        unsigned long long w20 = pack2(w0, w0);
        unsigned long long w21 = pack2(w1, w1);
        #pragma unroll
        for (int q = 0; q < 7; q++){
            ulonglong2 pr = ftu[f*8 + q];
            pfma(acc0[2*q  ], pr.x, w20);
            pfma(acc0[2*q+1], pr.y, w20);
            pfma(acc1[2*q  ], pr.x, w21);
            pfma(acc1[2*q+1], pr.y, w21);
        }
        ulonglong2 pr7 = ftu[f*8 + 7];
        pfma(acc0[14], pr7.x, w20);
        pfma(acc1[14], pr7.x, w21);
    }
    #pragma unroll
    for (int p = 0; p < 15; p++){
        float a, bb;
        unpack2(acc0[p], a, bb);
        ou[(2*p  )*129 + h0] = a;
        ou[(2*p+1)*129 + h0] = bb;
        unpack2(acc1[p], a, bb);
        ou[(2*p  )*129 + h1] = a;
        ou[(2*p+1)*129 + h1] = bb;
    }
    __syncthreads();

    if (t < Kc){
        float s = 0.f;
        for (int q = 0; q < Hc; q++) s += ou[t*129 + q];
        float mu = s / (float)Hc;
        float s2 = 0.f;
        for (int q = 0; q < Hc; q++){ float d = ou[t*129 + q] - mu; s2 += d*d; }
        smu[tile*32 + t] = mu;
        srs[tile*32 + t] = 1.f / sqrtf(s2 / (float)Hc + 1e-5f);
    }
    __syncthreads();

    float g0 = lg[h0], bb0 = lb[h0];
    float g1 = lg[h1], bb1 = lb[h1];
    #pragma unroll 5
    for (int r = 0; r < Kc; r++){
        float mu = smu[tile*32 + r], rs = srs[tile*32 + r];
        size_t o = ((size_t)base*Kc + r)*Hc;
        out[o + h0] = (ou[r*129 + h0] - mu)*rs*g0 + bb0;
        out[o + h1] = (ou[r*129 + h1] - mu)*rs*g1 + bb1;
    }
}

// ---------------------------------------------------------------------------
extern "C" void kernel_launch(void* const* d_in, const int* in_sizes, int n_in,
                              void* d_out, int out_size){
    const float* xyz    = (const float*)d_in[0];
    const float* mask   = (const float*)d_in[1];
    const float* node_w = (const float*)d_in[2];
    const float* node_b = (const float*)d_in[3];
    const float* edge_w = (const float*)d_in[4];
    const float* edge_b = (const float*)d_in[5];
    const float* ln_ng  = (const float*)d_in[6];
    const float* ln_nb  = (const float*)d_in[7];
    const float* ln_eg  = (const float*)d_in[8];
    const float* ln_eb  = (const float*)d_in[9];

    float* out = (float*)d_out;
    float* out_node = out;
    float* out_edge = out + (size_t)Bc*Lc*Hc;
    float* out_eidx = out_edge + (size_t)Bc*Lc*Kc*Hc;

    const int knn_smem = (3*Lc + Lc + QPB*Lc) * (int)sizeof(float); // 96 KB
    cudaFuncSetAttribute(knn_kernel, cudaFuncAttributeMaxDynamicSharedMemorySize, knn_smem);
    const int edge_smem = EDGE_SMEM_FLOATS * (int)sizeof(float);     // ~62.7 KB
    cudaFuncSetAttribute(edge_kernel, cudaFuncAttributeMaxDynamicSharedMemorySize, edge_smem);

    prep_kernel<<<(Bc*Lc + 255)/256, 256>>>(xyz, mask);
    knn_kernel<<<dim3(Lc/QPB, Bc), 256, knn_smem>>>(xyz, mask, out_eidx);
    node_kernel<<<(Bc*Lc)/4, 128>>>(xyz, node_w, node_b, ln_ng, ln_nb, out_node);
    edge_kernel<<<dim3(Lc/2, Bc), 128, edge_smem>>>(xyz, edge_w, edge_b, ln_eg, ln_eb, out_edge);
}

// round 4
// speedup vs baseline: 2.1633x; 1.0731x over previous
#include <cuda_runtime.h>

// Problem constants
#define Bc 2
#define Lc 2048
#define Kc 30
#define Hc 128
#define RBFN 16
#define NFN 267   // node features: 15 dir + 12 angle + 240 rbf
#define NFE 121   // edge features: 18 dir + 7 ori + 96 rbf
#define QPB 8     // knn queries per block (one per warp)

// Scratch (device globals: allocation-free rule)
__device__ int   g_eidx[Bc*Lc*Kc];
__device__ float g_O[Bc*Lc*9];
__device__ int   g_last[Bc];

struct F3 { float x, y, z; };
__device__ __forceinline__ F3 f3sub(F3 a, F3 b){ return {a.x-b.x, a.y-b.y, a.z-b.z}; }
__device__ __forceinline__ float dot3(F3 a, F3 b){ return a.x*b.x + a.y*b.y + a.z*b.z; }
__device__ __forceinline__ F3 cross3(F3 a, F3 b){
    return { a.y*b.z - a.z*b.y, a.z*b.x - a.x*b.z, a.x*b.y - a.y*b.x };
}
__device__ __forceinline__ F3 norm3v(F3 a){
    float n = sqrtf(dot3(a,a));
    float d = fmaxf(n, 1e-12f);
    return { a.x/d, a.y/d, a.z/d };
}
__device__ __forceinline__ F3 ld3(const float* p){ return { p[0], p[1], p[2] }; }
__device__ __forceinline__ float sgnf(float x){ return (x > 0.f) ? 1.f : ((x < 0.f) ? -1.f : 0.f); }

// packed f32x2 helpers
__device__ __forceinline__ unsigned long long pack2(float a, float b){
    unsigned long long r;
    asm("mov.b64 %0, {%1, %2};" : "=l"(r) : "f"(a), "f"(b));
    return r;
}
__device__ __forceinline__ void unpack2(unsigned long long v, float& a, float& b){
    asm("mov.b64 {%0, %1}, %2;" : "=f"(a), "=f"(b) : "l"(v));
}
__device__ __forceinline__ void pfma(unsigned long long& acc, unsigned long long a, unsigned long long b){
    asm("fma.rn.f32x2 %0, %1, %2, %0;" : "+l"(acc) : "l"(a), "l"(b));
}

// xyz layout: [B][L][6][3] row-major
__device__ __forceinline__ const float* atom_ptr(const float* xyz, int b, int l, int a){
    return xyz + (((size_t)(b*Lc + l))*6 + a)*3;
}
// chain point P(t) for X3 = xyz[:,:,:3] flattened to (3L,3)
__device__ __forceinline__ F3 ldP(const float* xyz, int b, int t){
    int r = t / 3, a = t - 3*r;
    return ld3(atom_ptr(xyz, b, r, a));
}

// ---------------------------------------------------------------------------
// prep: per-residue orientation frames O (padded) + last index per batch
// ---------------------------------------------------------------------------
__global__ void prep_kernel(const float* __restrict__ xyz, const float* __restrict__ mask){
    int gid = blockIdx.x*blockDim.x + threadIdx.x;
    if (blockIdx.x == 0 && threadIdx.x < 64){
        int b = threadIdx.x >> 5, lane = threadIdx.x & 31;
        float s = 0.f;
        for (int m = lane; m < Lc; m += 32) s += mask[b*Lc + m];
        #pragma unroll
        for (int o = 16; o; o >>= 1) s += __shfl_xor_sync(0xffffffffu, s, o);
        if (lane == 0) g_last[b] = (int)s - 1;
    }
    if (gid < Bc*Lc){
        int b = gid / Lc, l = gid % Lc;
        float o[9] = {0,0,0,0,0,0,0,0,0};
        if (l >= 1 && l <= Lc-3){
            F3 cm = ld3(atom_ptr(xyz,b,l-1,1));
            F3 c0 = ld3(atom_ptr(xyz,b,l  ,1));
            F3 cp = ld3(atom_ptr(xyz,b,l+1,1));
            F3 u2 = norm3v(f3sub(c0,cm));
            F3 u1 = norm3v(f3sub(cp,c0));
            F3 o1 = norm3v(f3sub(u2,u1));
            F3 n2 = norm3v(cross3(u2,u1));
            F3 o3 = cross3(o1,n2);
            o[0]=o1.x; o[1]=o1.y; o[2]=o1.z;
            o[3]=n2.x; o[4]=n2.y; o[5]=n2.z;
            o[6]=o3.x; o[7]=o3.y; o[8]=o3.z;
        }
        #pragma unroll
        for (int q = 0; q < 9; q++) g_O[(size_t)gid*9 + q] = o[q];
    }
}

// ---------------------------------------------------------------------------
// KNN: one warp per query. Exact top-K ascending distance, tie -> lower index.
// Per-lane top-3 in registers; selection via redux.sync (value, then index).
// ---------------------------------------------------------------------------
__device__ __forceinline__ void knn_insert3(float d, int j,
    float& v1, int& i1, float& v2, int& i2, float& v3, int& i3){
    if (d < v3){
        if (d < v2){
            if (d < v1){ v3=v2; i3=i2; v2=v1; i2=i1; v1=d; i1=j; }
            else       { v3=v2; i3=i2; v2=d;  i2=j; }
        } else         { v3=d;  i3=j; }
    }
}

__global__ void __launch_bounds__(256) knn_kernel(const float* __restrict__ xyz,
                                                  const float* __restrict__ mask,
                                                  float* __restrict__ out_eidx){
    extern __shared__ float dyns[];
    float* sca = dyns;              // 3*Lc
    float* smk = sca + 3*Lc;        // Lc
    float* sdall = smk + Lc;        // QPB*Lc

    int tid = threadIdx.x;
    int w = tid >> 5, lane = tid & 31;
    int b = blockIdx.y;
    int i = blockIdx.x*QPB + w;

    for (int j = tid; j < Lc; j += 256){
        const float* p = atom_ptr(xyz, b, j, 1);
        sca[j*3+0] = p[0]; sca[j*3+1] = p[1]; sca[j*3+2] = p[2];
        smk[j] = mask[b*Lc + j];
    }
    __syncthreads();

    float* sdr = sdall + w*Lc;
    float xi = sca[i*3], yi = sca[i*3+1], zi = sca[i*3+2];
    float mi = smk[i];

    // distance pass + row max
    float dmax = -1e30f;
    #pragma unroll 4
    for (int m = 0; m < 64; m++){
        int j = lane + 32*m;
        float dx = __fadd_rn(sca[j*3+0], -xi);
        float dy = __fadd_rn(sca[j*3+1], -yi);
        float dz = __fadd_rn(sca[j*3+2], -zi);
        float s  = __fadd_rn(__fadd_rn(__fmul_rn(dx,dx), __fmul_rn(dy,dy)), __fmul_rn(dz,dz));
        float D  = __fmul_rn(__fmul_rn(smk[j], mi), __fsqrt_rn(__fadd_rn(s, 1e-6f)));
        sdr[j] = D;
        dmax = fmaxf(dmax, D);
    }
    // all distances >= 0 -> float bits order == value order
    {
        unsigned mb = __reduce_max_sync(0xffffffffu, __float_as_uint(dmax));
        dmax = __uint_as_float(mb);
    }

    // mask adjust: Dadj = D + (1-m2)*Dmax, and build per-lane top-3
    float v1 = 1e38f, v2 = 1e38f, v3 = 1e38f;
    int   i1 = 0x7fffffff, i2 = 0x7fffffff, i3 = 0x7fffffff;
    #pragma unroll 4
    for (int m = 0; m < 64; m++){
        int j = lane + 32*m;
        float m2 = __fmul_rn(smk[j], mi);
        float d = __fadd_rn(sdr[j], __fmul_rn(__fadd_rn(1.0f, -m2), dmax));
        sdr[j] = d;
        knn_insert3(d, j, v1, i1, v2, i2, v3, i3);
    }

    size_t obase = (size_t)(b*Lc + i)*Kc;
    for (int it = 0; it < Kc; it++){
        unsigned myb = __float_as_uint(v1);
        unsigned kb = __reduce_min_sync(0xffffffffu, myb);
        unsigned cand = (myb == kb) ? (unsigned)i1 : 0xffffffffu;
        unsigned ib = __reduce_min_sync(0xffffffffu, cand);
        if (lane == 0){
            g_eidx[obase + it] = (int)ib;
            out_eidx[obase + it] = (float)ib;
        }
        if (myb == kb && (unsigned)i1 == ib){
            sdr[i1] = 1e38f;    // mark taken
            v1 = v2; i1 = i2;
            v2 = v3; i2 = i3;
            v3 = 1e38f; i3 = 0x7fffffff;
            if (v1 == 1e38f && it < Kc-1){
                // refill top-3 from remaining candidates
                v1 = v2 = v3 = 1e38f; i1 = i2 = i3 = 0x7fffffff;
                #pragma unroll 8
                for (int m = 0; m < 64; m++){
                    int j = lane + 32*m;
                    float d = sdr[j];
                    knn_insert3(d, j, v1, i1, v2, i2, v3, i3);
                }
            }
        }
    }
}

// ---------------------------------------------------------------------------
// Node: features (267) -> GEMM(267x128) -> LN.  4 rows per block, 128 threads.
// ---------------------------------------------------------------------------
__global__ void __launch_bounds__(128) node_kernel(const float* __restrict__ xyz,
                            const float* __restrict__ nw, const float* __restrict__ nb,
                            const float* __restrict__ lg, const float* __restrict__ lb,
                            float* __restrict__ out){
    __shared__ __align__(16) float ft[NFN*4];
    __shared__ float outs[4][Hc+1];
    __shared__ float smu[4], srs[4];

    int tid = threadIdx.x;
    int warp = tid >> 5, lane = tid & 31;
    int gid = blockIdx.x*4 + warp;
    int b = gid / Lc, l = gid % Lc;

    // per-warp feature computation for row `warp`
    {
        const float* ap = xyz + (size_t)gid*18;
        F3 A0 = ld3(ap+0), A1 = ld3(ap+3), A2 = ld3(ap+6);
        F3 A3 = ld3(ap+9), A4 = ld3(ap+12), A5 = ld3(ap+15);
        F3 u = norm3v(f3sub(A0,A1));
        F3 v = norm3v(f3sub(A1,A2));
        F3 fb = norm3v(f3sub(u,v));
        F3 fn = norm3v(cross3(u,v));
        F3 fc = cross3(fb,fn);

        if (lane < 15){
            // node_dir
            const int sel[5] = {0,2,3,4,5};
            int a = lane/3, d = lane%3;
            F3 Aa = (sel[a]==0)?A0:((sel[a]==2)?A2:((sel[a]==3)?A3:((sel[a]==4)?A4:A5)));
            F3 t = norm3v(f3sub(Aa, A1));
            F3 col = (d==0)?fb:((d==1)?fn:fc);
            ft[lane*4 + warp] = dot3(t, col);

            // node_rbf: pair `lane`
            const int r0[15] = {0,0,0,0,0,1,1,1,1,2,2,2,3,3,4};
            const int r1[15] = {1,2,3,4,5,2,3,4,5,3,4,5,4,5,5};
            F3 P[6] = {A0,A1,A2,A3,A4,A5};
            F3 dd = f3sub(P[r0[lane]], P[r1[lane]]);
            float Dn = sqrtf(dot3(dd,dd));
            #pragma unroll
            for (int q = 0; q < RBFN; q++){
                float t2 = (Dn - (float)q*(20.0f/15.0f)) * 0.8f;
                ft[(27 + lane*RBFN + q)*4 + warp] = __expf(-t2*t2);
            }
        } else if (lane < 18){
            // angles, slot s
            int s = lane - 15;
            int p = 3*l + s;
            float Dd = 0.f, Db = 0.f;
            if (p >= 1 && p <= 3*Lc - 3){
                int raw = p - 1;
                F3 P0 = ldP(xyz,b,raw),   P1 = ldP(xyz,b,raw+1);
                F3 P2 = ldP(xyz,b,raw+2), P3 = ldP(xyz,b,raw+3);
                F3 u2 = norm3v(f3sub(P1,P0));
                F3 u1 = norm3v(f3sub(P2,P1));
                F3 u0 = norm3v(f3sub(P3,P2));
                F3 n2 = norm3v(cross3(u2,u1));
                F3 n1 = norm3v(cross3(u1,u0));
                float cd = fminf(fmaxf(dot3(n2,n1), -1.f + 1e-7f), 1.f - 1e-7f);
                Dd = sgnf(dot3(u2,n1)) * acosf(cd);
                float cb = fminf(fmaxf(dot3(u2,u1), -1.f + 1e-7f), 1.f - 1e-7f);
                Db = acosf(cb);
            }
            float cDd = cosf(Dd), sDd = sinf(Dd), cDb = cosf(Db), sDb = sinf(Db);
            if (l == g_last[b]){ cDd = 0.f; sDd = 0.f; cDb = 0.f; sDb = 0.f; }
            ft[(15 + s)*4 + warp] = cDd;
            ft[(18 + s)*4 + warp] = sDd;
            ft[(21 + s)*4 + warp] = cDb;
            ft[(24 + s)*4 + warp] = sDb;
        }
    }
    __syncthreads();

    // GEMM: thread = column h, one LDS.128 per feature (4 rows)
    int h = tid;
    float bias = nb[h];
    unsigned long long acc0 = pack2(bias, bias);
    unsigned long long acc1 = pack2(bias, bias);
    const ulonglong2* ftu = reinterpret_cast<const ulonglong2*>(ft);
    for (int f = 0; f < NFN; f++){
        float wf = __ldg(nw + f*Hc + h);
        unsigned long long w2 = pack2(wf, wf);
        ulonglong2 a = ftu[f];
        pfma(acc0, a.x, w2);
        pfma(acc1, a.y, w2);
    }
    float y0,y1,y2,y3;
    unpack2(acc0, y0, y1);
    unpack2(acc1, y2, y3);
    outs[0][h] = y0; outs[1][h] = y1; outs[2][h] = y2; outs[3][h] = y3;
    __syncthreads();

    if (tid < 4){
        float s = 0.f;
        for (int q = 0; q < Hc; q++) s += outs[tid][q];
        float mu = s / (float)Hc;
        float s2 = 0.f;
        for (int q = 0; q < Hc; q++){ float d = outs[tid][q] - mu; s2 += d*d; }
        smu[tid] = mu;
        srs[tid] = 1.f / sqrtf(s2 / (float)Hc + 1e-5f);
    }
    __syncthreads();

    int row0 = blockIdx.x*4;
    float gh = lg[h], bh = lb[h];
    #pragma unroll
    for (int r = 0; r < 4; r++){
        out[(size_t)(row0 + r)*Hc + h] = (outs[r][h] - smu[r])*srs[r]*gh + bh;
    }
}

// ---------------------------------------------------------------------------
// Edge: 2 tiles per 128-thread block; 64 threads/tile, 2 ADJACENT cols/thread.
// LN staging buffer aliases the feature buffer (smem 62.7 -> 31.2 KB).
// ---------------------------------------------------------------------------
#define OSTR 130                       // LN staging row stride (keeps 8B align)
#define ETS  3900                      // per-tile buffer floats: max(121*32, 30*130)
#define EDGE_SMEM_FLOATS (2*ETS + 64 + 64 + 64)

__global__ void __launch_bounds__(128, 4) edge_kernel(const float* __restrict__ xyz,
                            const float* __restrict__ ew, const float* __restrict__ eb,
                            const float* __restrict__ lg, const float* __restrict__ lb,
                            float* __restrict__ out){
    extern __shared__ float es[];
    float* buf  = es;                               // [2][ETS]
    int*   sjn  = (int*)(buf + 2*ETS);              // [2][32]
    float* smu  = (float*)(sjn + 64);               // [2][32]
    float* srs  = smu + 64;                         // [2][32]

    int tid = threadIdx.x;
    int tile = tid >> 6;
    int t = tid & 63;
    int l = blockIdx.x*2 + tile;
    int b = blockIdx.y;
    int base = b*Lc + l;

    float* ft = buf + tile*ETS;   // feature buffer [NFE*32]
    float* ou = ft;               // aliased LN staging [Kc*OSTR]

    if (t < Kc) sjn[tile*32 + t] = g_eidx[(size_t)base*Kc + t];
    __syncthreads();

    if (t < 60){
        int k = t >> 1, sub = t & 1;
        int j = sjn[tile*32 + k];
        const float* api = xyz + (size_t)base*18;
        const float* apj = xyz + (size_t)(b*Lc + j)*18;
        F3 Ca = ld3(api + 3);   // atom 1 of i

        // frame of residue i (both subs compute it)
        F3 Ai0 = ld3(api+0), Ai2 = ld3(api+6);
        F3 u = norm3v(f3sub(Ai0, Ca));
        F3 v = norm3v(f3sub(Ca, Ai2));
        F3 fb = norm3v(f3sub(u,v));
        F3 fn = norm3v(cross3(u,v));
        F3 fc = cross3(fb,fn);

        if (sub == 0){
            // dir atoms 0..2 + rbf atoms 0..2
            #pragma unroll
            for (int a = 0; a < 3; a++){
                F3 tv = norm3v(f3sub(ld3(apj + a*3), Ca));
                ft[(a*3+0)*32 + k] = dot3(tv, fb);
                ft[(a*3+1)*32 + k] = dot3(tv, fn);
                ft[(a*3+2)*32 + k] = dot3(tv, fc);
            }
            #pragma unroll
            for (int a = 0; a < 3; a++){
                F3 d = f3sub(ld3(apj + a*3), Ca);
                float De = sqrtf(dot3(d,d));
                #pragma unroll
                for (int q = 0; q < RBFN; q++){
                    float t2 = (De - (float)q*(20.0f/15.0f))*0.8f;
                    ft[(25 + a*RBFN + q)*32 + k] = __expf(-t2*t2);
                }
            }
        } else {
            // dir atoms 3..5 + ori + rbf atoms 3..5
            #pragma unroll
            for (int a = 3; a < 6; a++){
                F3 tv = norm3v(f3sub(ld3(apj + a*3), Ca));
                ft[(a*3+0)*32 + k] = dot3(tv, fb);
                ft[(a*3+1)*32 + k] = dot3(tv, fn);
                ft[(a*3+2)*32 + k] = dot3(tv, fc);
            }
            // orientation features
            float Om[9], On[9];
            #pragma unroll
            for (int q = 0; q < 9; q++) Om[q] = g_O[(size_t)base*9 + q];
            #pragma unroll
            for (int q = 0; q < 9; q++) On[q] = g_O[(size_t)(b*Lc + j)*9 + q];
            F3 Cj = ld3(apj + 3);
            F3 dX = f3sub(Cj, Ca);
            float d0 = Om[0]*dX.x + Om[1]*dX.y + Om[2]*dX.z;
            float d1 = Om[3]*dX.x + Om[4]*dX.y + Om[5]*dX.z;
            float d2 = Om[6]*dX.x + Om[7]*dX.y + Om[8]*dX.z;
            float nn = sqrtf(d0*d0 + d1*d1 + d2*d2);
            float inv = 1.f / fmaxf(nn, 1e-12f);
            ft[18*32 + k] = d0*inv;
            ft[19*32 + k] = d1*inv;
            ft[20*32 + k] = d2*inv;
            // R = Om^T * On
            float R[3][3];
            #pragma unroll
            for (int ii = 0; ii < 3; ii++)
                #pragma unroll
                for (int m = 0; m < 3; m++)
                    R[ii][m] = Om[0*3+ii]*On[0*3+m] + Om[1*3+ii]*On[1*3+m] + Om[2*3+ii]*On[2*3+m];
            float Rxx = R[0][0], Ryy = R[1][1], Rzz = R[2][2];
            float mx = 0.5f*sqrtf(fabsf(1.f + Rxx - Ryy - Rzz));
            float my = 0.5f*sqrtf(fabsf(1.f - Rxx + Ryy - Rzz));
            float mz = 0.5f*sqrtf(fabsf(1.f - Rxx - Ryy + Rzz));
            float qx = sgnf(R[2][1] - R[1][2]) * mx;
            float qy = sgnf(R[0][2] - R[2][0]) * my;
            float qz = sgnf(R[1][0] - R[0][1]) * mz;
            float qw = sqrtf(fmaxf(1.f + Rxx + Ryy + Rzz, 0.f)) * 0.5f;
            float qn = sqrtf(qx*qx + qy*qy + qz*qz + qw*qw);
            float qi = 1.f / fmaxf(qn, 1e-12f);
            ft[21*32 + k] = qx*qi;
            ft[22*32 + k] = qy*qi;
            ft[23*32 + k] = qz*qi;
            ft[24*32 + k] = qw*qi;
            // rbf atoms 3..5
            #pragma unroll
            for (int a = 3; a < 6; a++){
                F3 d = f3sub(ld3(apj + a*3), Ca);
                float De = sqrtf(dot3(d,d));
                #pragma unroll
                for (int q = 0; q < RBFN; q++){
                    float t2 = (De - (float)q*(20.0f/15.0f))*0.8f;
                    ft[(25 + a*RBFN + q)*32 + k] = __expf(-t2*t2);
                }
            }
        }
    }
    __syncthreads();

    // GEMM: thread = adjacent columns (2t, 2t+1); 8 LDS.128 per feature
    int h0 = 2*t, h1 = 2*t + 1;
    float b0 = eb[h0], b1 = eb[h1];
    unsigned long long acc0[15], acc1[15];
    #pragma unroll
    for (int p = 0; p < 15; p++){ acc0[p] = pack2(b0, b0); acc1[p] = pack2(b1, b1); }

    const ulonglong2* ftu = reinterpret_cast<const ulonglong2*>(ft); // index f*8 + q
    const float2* ew2 = reinterpret_cast<const float2*>(ew);
    #pragma unroll 2
    for (int f = 0; f < NFE; f++){
        float2 wp = __ldg(ew2 + f*(Hc/2) + t);
        unsigned long long w20 = pack2(wp.x, wp.x);
        unsigned long long w21 = pack2(wp.y, wp.y);
        #pragma unroll
        for (int q = 0; q < 7; q++){
            ulonglong2 pr = ftu[f*8 + q];
            pfma(acc0[2*q  ], pr.x, w20);
            pfma(acc0[2*q+1], pr.y, w20);
            pfma(acc1[2*q  ], pr.x, w21);
            pfma(acc1[2*q+1], pr.y, w21);
        }
        ulonglong2 pr7 = ftu[f*8 + 7];
        pfma(acc0[14], pr7.x, w20);
        pfma(acc1[14], pr7.x, w21);
    }
    __syncthreads();   // all tile threads done reading ft -> safe to overwrite (alias)

    #pragma unroll
    for (int p = 0; p < 15; p++){
        float a0lo, a0hi, a1lo, a1hi;
        unpack2(acc0[p], a0lo, a0hi);
        unpack2(acc1[p], a1lo, a1hi);
        // row 2p: cols (h0,h1); row 2p+1: cols (h0,h1). 8B-aligned STS.64.
        *reinterpret_cast<unsigned long long*>(ou + (2*p  )*OSTR + h0) = pack2(a0lo, a1lo);
        *reinterpret_cast<unsigned long long*>(ou + (2*p+1)*OSTR + h0) = pack2(a0hi, a1hi);
    }
    __syncthreads();

    if (t < Kc){
        float s = 0.f;
        for (int q = 0; q < Hc; q++) s += ou[t*OSTR + q];
        float mu = s / (float)Hc;
        float s2 = 0.f;
        for (int q = 0; q < Hc; q++){ float d = ou[t*OSTR + q] - mu; s2 += d*d; }
        smu[tile*32 + t] = mu;
        srs[tile*32 + t] = 1.f / sqrtf(s2 / (float)Hc + 1e-5f);
    }
    __syncthreads();

    float g0 = lg[h0], bb0 = lb[h0];
    float g1 = lg[h1], bb1 = lb[h1];
    #pragma unroll 5
    for (int r = 0; r < Kc; r++){
        float mu = smu[tile*32 + r], rs = srs[tile*32 + r];
        float2 y = *reinterpret_cast<const float2*>(ou + r*OSTR + h0);
        float2 o2;
        o2.x = (y.x - mu)*rs*g0 + bb0;
        o2.y = (y.y - mu)*rs*g1 + bb1;
        size_t o = ((size_t)base*Kc + r)*Hc;
        *reinterpret_cast<float2*>(out + o + h0) = o2;
    }
}

// ---------------------------------------------------------------------------
extern "C" void kernel_launch(void* const* d_in, const int* in_sizes, int n_in,
                              void* d_out, int out_size){
    const float* xyz    = (const float*)d_in[0];
    const float* mask   = (const float*)d_in[1];
    const float* node_w = (const float*)d_in[2];
    const float* node_b = (const float*)d_in[3];
    const float* edge_w = (const float*)d_in[4];
    const float* edge_b = (const float*)d_in[5];
    const float* ln_ng  = (const float*)d_in[6];
    const float* ln_nb  = (const float*)d_in[7];
    const float* ln_eg  = (const float*)d_in[8];
    const float* ln_eb  = (const float*)d_in[9];

    float* out = (float*)d_out;
    float* out_node = out;
    float* out_edge = out + (size_t)Bc*Lc*Hc;
    float* out_eidx = out_edge + (size_t)Bc*Lc*Kc*Hc;

    const int knn_smem = (3*Lc + Lc + QPB*Lc) * (int)sizeof(float); // 96 KB
    cudaFuncSetAttribute(knn_kernel, cudaFuncAttributeMaxDynamicSharedMemorySize, knn_smem);
    const int edge_smem = EDGE_SMEM_FLOATS * (int)sizeof(float);     // ~31.2 KB
    cudaFuncSetAttribute(edge_kernel, cudaFuncAttributeMaxDynamicSharedMemorySize, edge_smem);

    prep_kernel<<<(Bc*Lc + 255)/256, 256>>>(xyz, mask);
    knn_kernel<<<dim3(Lc/QPB, Bc), 256, knn_smem>>>(xyz, mask, out_eidx);
    node_kernel<<<(Bc*Lc)/4, 128>>>(xyz, node_w, node_b, ln_ng, ln_nb, out_node);
    edge_kernel<<<dim3(Lc/2, Bc), 128, edge_smem>>>(xyz, edge_w, edge_b, ln_eg, ln_eb, out_edge);
}